// round 7
// baseline (speedup 1.0000x reference)
#include <cuda_runtime.h>
#include <cuda_bf16.h>
#include <math.h>
#include <stdint.h>

#define T_STEPS 50
#define BB      1024
#define S_DIM   32
#define D_DIM   600
#define H_DIM   600
#define A_DIM   6
#define E_DIM   1024
#define G3_DIM  1800
#define MIN_STD 0.1f

#define SZ_SB   ((size_t)T_STEPS * BB * S_DIM)
#define SZ_DB   ((size_t)T_STEPS * BB * D_DIM)
#define OFF_PM    ((size_t)0)
#define OFF_PS    (SZ_SB)
#define OFF_PRIOR (2 * SZ_SB)
#define OFF_DET1  (3 * SZ_SB)
#define OFF_QM    (3 * SZ_SB + SZ_DB)
#define OFF_QS    (4 * SZ_SB + SZ_DB)
#define OFF_POST  (5 * SZ_SB + SZ_DB)
#define OFF_DET2  (6 * SZ_SB + SZ_DB)

// ---------------- static device scratch ----------------
__device__ __nv_bfloat16 g_Wih_h[G3_DIM * D_DIM], g_Wih_l[G3_DIM * D_DIM];
__device__ __nv_bfloat16 g_Whh_h[G3_DIM * D_DIM], g_Whh_l[G3_DIM * D_DIM];
__device__ __nv_bfloat16 g_Wp1_h[H_DIM * D_DIM],  g_Wp1_l[H_DIM * D_DIM];
__device__ __nv_bfloat16 g_Wq1d_h[H_DIM * D_DIM], g_Wq1d_l[H_DIM * D_DIM];
__device__ __nv_bfloat16 g_Wq1e_h[H_DIM * E_DIM], g_Wq1e_l[H_DIM * E_DIM];
__device__ __nv_bfloat16 g_Wp2_h[64 * H_DIM],     g_Wp2_l[64 * H_DIM];
__device__ __nv_bfloat16 g_Wq2_h[64 * H_DIM],     g_Wq2_l[64 * H_DIM];
__device__ __nv_bfloat16 g_Ws_h[H_DIM * S_DIM],   g_Ws_l[H_DIM * S_DIM];   // W_in[:,6:38]
__device__ __nv_bfloat16 g_enc_h[(size_t)T_STEPS * BB * E_DIM];
__device__ __nv_bfloat16 g_enc_l[(size_t)T_STEPS * BB * E_DIM];
__device__ float         g_genc[(size_t)T_STEPS * BB * D_DIM];
__device__ float         g_rnnpre[(size_t)T_STEPS * BB * H_DIM];           // b_in + act@Wa
__device__ __nv_bfloat16 g_rnn_h[BB * H_DIM], g_rnn_l[BB * H_DIM];
__device__ __nv_bfloat16 g_det_h[BB * D_DIM], g_det_l[BB * D_DIM];
__device__ __nv_bfloat16 g_hp_h [BB * H_DIM], g_hp_l [BB * H_DIM];
__device__ __nv_bfloat16 g_hq_h [BB * H_DIM], g_hq_l [BB * H_DIM];
__device__ __nv_bfloat16 g_st_h [BB * S_DIM], g_st_l [BB * S_DIM];         // stoch split (init & post)
__device__ float g_gi[BB * G3_DIM], g_gh[BB * G3_DIM];

__device__ __forceinline__ float eluf(float x)      { return x > 0.f ? x : expm1f(x); }
__device__ __forceinline__ float sigmoidf_(float x) { return 1.f / (1.f + expf(-x)); }
__device__ __forceinline__ float softplusf_(float x){ return fmaxf(x, 0.f) + log1pf(expf(-fabsf(x))); }

// ---------------- PTX helpers ----------------
__device__ __forceinline__ uint32_t smem_u32(const void* p) {
    uint32_t a;
    asm("{ .reg .u64 t; cvta.to.shared.u64 t, %1; cvt.u32.u64 %0, t; }" : "=r"(a) : "l"(p));
    return a;
}
__device__ __forceinline__ void cpa16(uint32_t dst, const void* src, int nb) {
    asm volatile("cp.async.cg.shared.global [%0], [%1], 16, %2;" :: "r"(dst), "l"(src), "r"(nb));
}
#define CP_COMMIT() asm volatile("cp.async.commit_group;" ::: "memory")

__device__ __forceinline__ void ldsm4(uint32_t* r, uint32_t addr) {
    asm volatile("ldmatrix.sync.aligned.m8n8.x4.shared.b16 {%0,%1,%2,%3}, [%4];"
        : "=r"(r[0]), "=r"(r[1]), "=r"(r[2]), "=r"(r[3]) : "r"(addr));
}
__device__ __forceinline__ void mma16816(float* d, const uint32_t* a, const uint32_t* b) {
    asm volatile("mma.sync.aligned.m16n8k16.row.col.f32.bf16.bf16.f32 "
        "{%0,%1,%2,%3}, {%4,%5,%6,%7}, {%8,%9}, {%0,%1,%2,%3};"
        : "+f"(d[0]), "+f"(d[1]), "+f"(d[2]), "+f"(d[3])
        : "r"(a[0]), "r"(a[1]), "r"(a[2]), "r"(a[3]), "r"(b[0]), "r"(b[1]));
}

// ---------------- GEMM param set ----------------
// modes: act 0 = none, 1 = ELU, 2 = dist epilogue (heads)
struct TSet {
    const __nv_bfloat16 *Ahi, *Alo;   // [M,K]
    const __nv_bfloat16 *Whi, *Wlo;   // [N,K]
    const float *bias;                // [N] or null
    const float *extra;               // [M,N] or null
    float *Cf;                        // fp32 out or null
    __nv_bfloat16 *Chi, *Clo;         // bf16-split out or null
    // mode 2 (dist):
    const float *eps;                 // [B,32] step slice
    float *m_o, *s_o, *samp_o;        // [B,32] step slices
    __nv_bfloat16 *sp_h, *sp_l;       // sample bf16 split (post carry) or null
};

#define BMT 128
#define RSB 144                       // row stride bytes: 128B data + 16B pad

template<int BNT, int THREADS>
__global__ void __launch_bounds__(THREADS, 1)
mma_gemm(TSet s0, TSet s1, int N, int K, int KC, int act)
{
    extern __shared__ char smraw[];
    constexpr int ASZ = BMT * RSB;
    constexpr int WSZ = BNT * RSB;
    constexpr int STG = 2 * ASZ + 2 * WSZ;
    const TSet s = blockIdx.z ? s1 : s0;
    const int tid = threadIdx.x;
    const int m0 = blockIdx.y * BMT, n0 = blockIdx.x * BNT;
    const uint32_t sb = smem_u32(smraw);
    const int Kb = K * 2;

    const int wid = tid >> 5, lane = tid & 31;
    const int wm = wid & 3;                 // 4 warps along M (32 rows each)
    const int wn = wid >> 2;                // THREADS/128 warps along N (32 cols each)

    const int arow  = lane & 15;
    const int akoff = (lane >> 4) * 16;
    const int brow  = (lane & 7) + ((lane >> 4) << 3);
    const int bkoff = ((lane >> 3) & 1) * 16;

    float acc[2][4][4];
#pragma unroll
    for (int i = 0; i < 2; i++)
#pragma unroll
        for (int j = 0; j < 4; j++)
#pragma unroll
            for (int q = 0; q < 4; q++) acc[i][j][q] = 0.f;

    auto load_stage = [&](int kc) {
        const uint32_t base = sb + (uint32_t)(kc & 1) * STG;
        const int k0b = kc * 128;
        constexpr int AIT = 2048 / THREADS;            // A: 2 x 128 x 8 ops
        #pragma unroll
        for (int v = 0; v < AIT; v++) {
            const int idx  = v * THREADS + tid;
            const int half = idx >> 10, r = (idx >> 3) & 127, j = idx & 7;
            const int off  = k0b + j * 16;
            const char* src = (const char*)(half ? s.Alo : s.Ahi);
            const int nb = (off + 16 <= Kb) ? 16 : 0;
            const char* p = nb ? src + (size_t)(m0 + r) * Kb + off : src;
            cpa16(base + half * ASZ + r * RSB + j * 16, p, nb);
        }
        constexpr int WIT = (BNT * 16) / THREADS;      // W: 2 x BNT x 8 ops
        #pragma unroll
        for (int v = 0; v < WIT; v++) {
            const int idx  = v * THREADS + tid;
            const int half = idx / (BNT * 8);
            const int r    = (idx >> 3) % BNT;
            const int j    = idx & 7;
            const int off  = k0b + j * 16;
            const char* src = (const char*)(half ? s.Wlo : s.Whi);
            const int nb = (off + 16 <= Kb && (n0 + r) < N) ? 16 : 0;
            const char* p = nb ? src + (size_t)(n0 + r) * Kb + off : src;
            cpa16(base + 2 * ASZ + half * WSZ + r * RSB + j * 16, p, nb);
        }
        CP_COMMIT();
    };

    load_stage(0);
    for (int kc = 0; kc < KC; kc++) {
        if (kc + 1 < KC) { load_stage(kc + 1); asm volatile("cp.async.wait_group 1;" ::: "memory"); }
        else             {                      asm volatile("cp.async.wait_group 0;" ::: "memory"); }
        __syncthreads();
        const uint32_t base = sb + (uint32_t)(kc & 1) * STG;

        #pragma unroll
        for (int k16 = 0; k16 < 4; k16++) {
            uint32_t a_h[2][4], a_l[2][4], b_h[2][4], b_l[2][4];
            const uint32_t Ah0 = base + (wm * 32 + arow) * RSB + k16 * 32 + akoff;
            ldsm4(a_h[0], Ah0);           ldsm4(a_h[1], Ah0 + 16 * RSB);
            ldsm4(a_l[0], Ah0 + ASZ);     ldsm4(a_l[1], Ah0 + ASZ + 16 * RSB);
            const uint32_t Wh0 = base + 2 * ASZ + (wn * 32 + brow) * RSB + k16 * 32 + bkoff;
            ldsm4(b_h[0], Wh0);           ldsm4(b_h[1], Wh0 + 16 * RSB);
            ldsm4(b_l[0], Wh0 + WSZ);     ldsm4(b_l[1], Wh0 + WSZ + 16 * RSB);

            #pragma unroll
            for (int tm = 0; tm < 2; tm++)
                #pragma unroll
                for (int g = 0; g < 2; g++)
                    #pragma unroll
                    for (int sub = 0; sub < 2; sub++) {
                        float* d = acc[tm][g * 2 + sub];
                        mma16816(d, a_h[tm], &b_h[g][sub * 2]);
                        mma16816(d, a_h[tm], &b_l[g][sub * 2]);
                        mma16816(d, a_l[tm], &b_h[g][sub * 2]);
                    }
        }
        __syncthreads();
    }

    if (act != 2) {
        // -------- standard fused epilogue from fragments --------
        #pragma unroll
        for (int nt = 0; nt < 4; nt++) {
            const int gc = n0 + wn * 32 + nt * 8 + ((lane & 3) << 1);
            if (gc >= N) continue;
            const float b0 = s.bias ? s.bias[gc]     : 0.f;
            const float b1 = s.bias ? s.bias[gc + 1] : 0.f;
            #pragma unroll
            for (int tm = 0; tm < 2; tm++) {
                const int r0 = m0 + wm * 32 + tm * 16 + (lane >> 2);
                #pragma unroll
                for (int hh = 0; hh < 2; hh++) {
                    const int gr = r0 + hh * 8;
                    float v0 = acc[tm][nt][hh * 2 + 0] + b0;
                    float v1 = acc[tm][nt][hh * 2 + 1] + b1;
                    if (s.extra) {
                        v0 += s.extra[(size_t)gr * N + gc];
                        v1 += s.extra[(size_t)gr * N + gc + 1];
                    }
                    if (act == 1) { v0 = eluf(v0); v1 = eluf(v1); }
                    if (s.Cf) {
                        s.Cf[(size_t)gr * N + gc]     = v0;
                        s.Cf[(size_t)gr * N + gc + 1] = v1;
                    }
                    if (s.Chi) {
                        const __nv_bfloat16 h0 = __float2bfloat16(v0);
                        const __nv_bfloat16 h1 = __float2bfloat16(v1);
                        s.Chi[(size_t)gr * N + gc]     = h0;
                        s.Chi[(size_t)gr * N + gc + 1] = h1;
                        s.Clo[(size_t)gr * N + gc]     = __float2bfloat16(v0 - __bfloat162float(h0));
                        s.Clo[(size_t)gr * N + gc + 1] = __float2bfloat16(v1 - __bfloat162float(h1));
                    }
                }
            }
        }
    } else {
        // -------- dist epilogue (heads, N==64): stage C -> softplus/reparam --------
        float* smC = (float*)smraw;             // [128][65]
        #pragma unroll
        for (int nt = 0; nt < 4; nt++) {
            const int c = wn * 32 + nt * 8 + ((lane & 3) << 1);
            const float b0 = s.bias[c], b1 = s.bias[c + 1];
            #pragma unroll
            for (int tm = 0; tm < 2; tm++) {
                const int r0 = wm * 32 + tm * 16 + (lane >> 2);
                #pragma unroll
                for (int hh = 0; hh < 2; hh++) {
                    smC[(r0 + hh * 8) * 65 + c]     = acc[tm][nt][hh * 2 + 0] + b0;
                    smC[(r0 + hh * 8) * 65 + c + 1] = acc[tm][nt][hh * 2 + 1] + b1;
                }
            }
        }
        __syncthreads();
        for (int i = tid; i < 128 * S_DIM; i += THREADS) {
            const int r = i >> 5, sx = i & 31;
            const float mean = smC[r * 65 + sx];
            const float sdv  = softplusf_(smC[r * 65 + 32 + sx]) + MIN_STD;
            const size_t gidx = (size_t)(m0 + r) * S_DIM + sx;
            s.m_o[gidx] = mean;
            s.s_o[gidx] = sdv;
            const float samp = fmaf(sdv, s.eps[gidx], mean);
            s.samp_o[gidx] = samp;
            if (s.sp_h) {
                const __nv_bfloat16 h = __float2bfloat16(samp);
                s.sp_h[gidx] = h;
                s.sp_l[gidx] = __float2bfloat16(samp - __bfloat162float(h));
            }
        }
    }
}

// ---------------- prep: fp32 -> bf16 hi/lo split ----------------
__global__ void wprep(const float* __restrict__ src, int pitch, int c0, int rows, int K,
                      __nv_bfloat16* __restrict__ hi, __nv_bfloat16* __restrict__ lo)
{
    const int total = rows * K;
    for (int i = blockIdx.x * blockDim.x + threadIdx.x; i < total; i += gridDim.x * blockDim.x) {
        const float v = src[(size_t)(i / K) * pitch + c0 + (i % K)];
        const __nv_bfloat16 h = __float2bfloat16(v);
        hi[i] = h;
        lo[i] = __float2bfloat16(v - __bfloat162float(h));
    }
}

// ---------------- prep: rnn_pre[t,b,h] = b_in[h] + act[t,b,:]@W_in[h,:6] ----------------
__global__ void rnnpre_kernel(const float* __restrict__ actions, const float* __restrict__ W_in,
                              const float* __restrict__ b_in, float* __restrict__ out)
{
    const size_t total = (size_t)T_STEPS * BB * H_DIM;
    for (size_t i = (size_t)blockIdx.x * blockDim.x + threadIdx.x; i < total;
         i += (size_t)gridDim.x * blockDim.x) {
        const size_t tb = i / H_DIM;
        const int h = (int)(i % H_DIM);
        float acc = b_in[h];
        const float* a = actions + tb * A_DIM;
        #pragma unroll
        for (int k = 0; k < A_DIM; k++) acc = fmaf(a[k], W_in[h * 38 + k], acc);
        out[i] = acc;
    }
}

// ---------------- GRU gates ----------------
__global__ void gru_gate_kernel(const float* __restrict__ gi, const float* __restrict__ gh,
                                const float* __restrict__ det_prev,
                                float* __restrict__ o1, float* __restrict__ o2,
                                __nv_bfloat16* __restrict__ dhi, __nv_bfloat16* __restrict__ dlo)
{
    const int idx = blockIdx.x * blockDim.x + threadIdx.x;
    if (idx >= BB * D_DIM) return;
    const int b = idx / D_DIM, j = idx % D_DIM;
    const float* gib = gi + (size_t)b * G3_DIM;
    const float* ghb = gh + (size_t)b * G3_DIM;
    const float r = sigmoidf_(gib[j] + ghb[j]);
    const float z = sigmoidf_(gib[D_DIM + j] + ghb[D_DIM + j]);
    const float n = tanhf(gib[2 * D_DIM + j] + r * ghb[2 * D_DIM + j]);
    const float d = (1.f - z) * n + z * det_prev[idx];
    o1[idx] = d; o2[idx] = d;
    const __nv_bfloat16 hh = __float2bfloat16(d);
    dhi[idx] = hh;
    dlo[idx] = __float2bfloat16(d - __bfloat162float(hh));
}

// ---------------- host launcher ----------------
extern "C" void kernel_launch(void* const* d_in, const int* in_sizes, int n_in,
                              void* d_out, int out_size) {
    const float* encoded    = (const float*)d_in[1];
    const float* actions    = (const float*)d_in[2];
    const float* init_stoch = (const float*)d_in[3];
    const float* init_det   = (const float*)d_in[4];
    const float* noise_p    = (const float*)d_in[5];
    const float* noise_q    = (const float*)d_in[6];
    const float* W_in = (const float*)d_in[7];
    const float* b_in = (const float*)d_in[8];
    const float* W_ih = (const float*)d_in[9];
    const float* W_hh = (const float*)d_in[10];
    const float* b_ih = (const float*)d_in[11];
    const float* b_hh = (const float*)d_in[12];
    const float* Wp1  = (const float*)d_in[13];
    const float* bp1  = (const float*)d_in[14];
    const float* Wp2  = (const float*)d_in[15];
    const float* bp2  = (const float*)d_in[16];
    const float* Wq1  = (const float*)d_in[17];
    const float* bq1  = (const float*)d_in[18];
    const float* Wq2  = (const float*)d_in[19];
    const float* bq2  = (const float*)d_in[20];
    float* out = (float*)d_out;

    __nv_bfloat16 *Wih_h, *Wih_l, *Whh_h, *Whh_l, *Wp1_h, *Wp1_l, *Wq1d_h, *Wq1d_l;
    __nv_bfloat16 *Wq1e_h, *Wq1e_l, *Wp2_h, *Wp2_l, *Wq2_h, *Wq2_l, *Ws_h, *Ws_l;
    __nv_bfloat16 *enc_h, *enc_l, *rnn_h, *rnn_l, *det_h, *det_l, *hp_h, *hp_l, *hq_h, *hq_l;
    __nv_bfloat16 *st_h, *st_l;
    float *genc, *rnnpre, *gi, *gh;
    cudaGetSymbolAddress((void**)&Wih_h, g_Wih_h);   cudaGetSymbolAddress((void**)&Wih_l, g_Wih_l);
    cudaGetSymbolAddress((void**)&Whh_h, g_Whh_h);   cudaGetSymbolAddress((void**)&Whh_l, g_Whh_l);
    cudaGetSymbolAddress((void**)&Wp1_h, g_Wp1_h);   cudaGetSymbolAddress((void**)&Wp1_l, g_Wp1_l);
    cudaGetSymbolAddress((void**)&Wq1d_h, g_Wq1d_h); cudaGetSymbolAddress((void**)&Wq1d_l, g_Wq1d_l);
    cudaGetSymbolAddress((void**)&Wq1e_h, g_Wq1e_h); cudaGetSymbolAddress((void**)&Wq1e_l, g_Wq1e_l);
    cudaGetSymbolAddress((void**)&Wp2_h, g_Wp2_h);   cudaGetSymbolAddress((void**)&Wp2_l, g_Wp2_l);
    cudaGetSymbolAddress((void**)&Wq2_h, g_Wq2_h);   cudaGetSymbolAddress((void**)&Wq2_l, g_Wq2_l);
    cudaGetSymbolAddress((void**)&Ws_h, g_Ws_h);     cudaGetSymbolAddress((void**)&Ws_l, g_Ws_l);
    cudaGetSymbolAddress((void**)&enc_h, g_enc_h);   cudaGetSymbolAddress((void**)&enc_l, g_enc_l);
    cudaGetSymbolAddress((void**)&rnn_h, g_rnn_h);   cudaGetSymbolAddress((void**)&rnn_l, g_rnn_l);
    cudaGetSymbolAddress((void**)&det_h, g_det_h);   cudaGetSymbolAddress((void**)&det_l, g_det_l);
    cudaGetSymbolAddress((void**)&hp_h, g_hp_h);     cudaGetSymbolAddress((void**)&hp_l, g_hp_l);
    cudaGetSymbolAddress((void**)&hq_h, g_hq_h);     cudaGetSymbolAddress((void**)&hq_l, g_hq_l);
    cudaGetSymbolAddress((void**)&st_h, g_st_h);     cudaGetSymbolAddress((void**)&st_l, g_st_l);
    cudaGetSymbolAddress((void**)&genc, g_genc);     cudaGetSymbolAddress((void**)&rnnpre, g_rnnpre);
    cudaGetSymbolAddress((void**)&gi, g_gi);         cudaGetSymbolAddress((void**)&gh, g_gh);

    const int SM128 = 2 * (2 * BMT * RSB + 2 * 128 * RSB);  // 147456
    const int SM64  = 2 * (2 * BMT * RSB + 2 * 64 * RSB);   // 110592
    cudaFuncSetAttribute(mma_gemm<128, 512>, cudaFuncAttributeMaxDynamicSharedMemorySize, SM128);
    cudaFuncSetAttribute(mma_gemm<64, 256>,  cudaFuncAttributeMaxDynamicSharedMemorySize, SM64);

    TSet z{};   // zero template

    // ---- once-per-replay prep ----
    wprep<<<4096, 256>>>(W_ih, D_DIM, 0, G3_DIM, D_DIM, Wih_h, Wih_l);
    wprep<<<4096, 256>>>(W_hh, D_DIM, 0, G3_DIM, D_DIM, Whh_h, Whh_l);
    wprep<<<2048, 256>>>(Wp1, D_DIM, 0, H_DIM, D_DIM, Wp1_h, Wp1_l);
    wprep<<<2048, 256>>>(Wq1, D_DIM + E_DIM, 0, H_DIM, D_DIM, Wq1d_h, Wq1d_l);
    wprep<<<2048, 256>>>(Wq1, D_DIM + E_DIM, D_DIM, H_DIM, E_DIM, Wq1e_h, Wq1e_l);
    wprep<<<256, 256>>>(Wp2, H_DIM, 0, 64, H_DIM, Wp2_h, Wp2_l);
    wprep<<<256, 256>>>(Wq2, H_DIM, 0, 64, H_DIM, Wq2_h, Wq2_l);
    wprep<<<128, 256>>>(W_in, 38, 6, H_DIM, S_DIM, Ws_h, Ws_l);
    wprep<<<16384, 256>>>(encoded, E_DIM, 0, T_STEPS * BB, E_DIM, enc_h, enc_l);
    wprep<<<256, 256>>>(init_stoch, S_DIM, 0, BB, S_DIM, st_h, st_l);
    wprep<<<2048, 256>>>(init_det, D_DIM, 0, BB, D_DIM, det_h, det_l);   // REQUIRED: t=0 GRU carry
    rnnpre_kernel<<<32768, 256>>>(actions, W_in, b_in, rnnpre);

    // genc = encoded @ Wq1[:,600:]^T   [51200 x 600], K=1024
    {
        TSet s = z;
        s.Ahi = enc_h; s.Alo = enc_l; s.Whi = Wq1e_h; s.Wlo = Wq1e_l; s.Cf = genc;
        mma_gemm<128, 512><<<dim3(5, T_STEPS * BB / BMT, 1), 512, SM128>>>(s, s, H_DIM, E_DIM, 16, 0);
    }
    // rnn(t=0) = elu(rnn_pre[0] + init_stoch @ Ws^T)
    {
        TSet s = z;
        s.Ahi = st_h; s.Alo = st_l; s.Whi = Ws_h; s.Wlo = Ws_l;
        s.extra = rnnpre; s.Chi = rnn_h; s.Clo = rnn_l;
        mma_gemm<128, 512><<<dim3(5, BB / BMT, 1), 512, SM128>>>(s, s, H_DIM, S_DIM, 1, 1);
    }

    // ---- sequential rollout (5 launches/step; last step 4) ----
    for (int t = 0; t < T_STEPS; t++) {
        const float* det_prev_f = (t == 0) ? init_det : out + OFF_DET1 + (size_t)(t - 1) * BB * D_DIM;
        float* det1 = out + OFF_DET1 + (size_t)t * BB * D_DIM;
        float* det2 = out + OFF_DET2 + (size_t)t * BB * D_DIM;

        {   // gi = rnn @ W_ih^T + b_ih ; gh = det_prev @ W_hh^T + b_hh   (N=1800, K=600)
            TSet sA = z, sB = z;
            sA.Ahi = rnn_h; sA.Alo = rnn_l; sA.Whi = Wih_h; sA.Wlo = Wih_l; sA.bias = b_ih; sA.Cf = gi;
            sB.Ahi = det_h; sB.Alo = det_l; sB.Whi = Whh_h; sB.Wlo = Whh_l; sB.bias = b_hh; sB.Cf = gh;
            mma_gemm<128, 512><<<dim3(15, BB / BMT, 2), 512, SM128>>>(sA, sB, G3_DIM, D_DIM, 10, 0);
        }

        gru_gate_kernel<<<(BB * D_DIM + 255) / 256, 256>>>(gi, gh, det_prev_f, det1, det2, det_h, det_l);

        {   // hp = elu(det @ Wp1^T + bp1) ; hq = elu(det @ Wq1d^T + genc_t + bq1)   (N=600, K=600)
            TSet sP = z, sQ = z;
            sP.Ahi = det_h; sP.Alo = det_l; sP.Whi = Wp1_h; sP.Wlo = Wp1_l; sP.bias = bp1;
            sP.Chi = hp_h; sP.Clo = hp_l;
            sQ.Ahi = det_h; sQ.Alo = det_l; sQ.Whi = Wq1d_h; sQ.Wlo = Wq1d_l; sQ.bias = bq1;
            sQ.extra = genc + (size_t)t * BB * D_DIM; sQ.Chi = hq_h; sQ.Clo = hq_l;
            mma_gemm<128, 512><<<dim3(5, BB / BMT, 2), 512, SM128>>>(sP, sQ, H_DIM, D_DIM, 10, 1);
        }

        {   // heads + dist fused: z=0 prior side, z=1 posterior side (+post split carry)
            TSet sP = z, sQ = z;
            sP.Ahi = hp_h; sP.Alo = hp_l; sP.Whi = Wp2_h; sP.Wlo = Wp2_l; sP.bias = bp2;
            sP.eps = noise_p + (size_t)t * BB * S_DIM;
            sP.m_o = out + OFF_PM + (size_t)t * BB * S_DIM;
            sP.s_o = out + OFF_PS + (size_t)t * BB * S_DIM;
            sP.samp_o = out + OFF_PRIOR + (size_t)t * BB * S_DIM;
            sQ.Ahi = hq_h; sQ.Alo = hq_l; sQ.Whi = Wq2_h; sQ.Wlo = Wq2_l; sQ.bias = bq2;
            sQ.eps = noise_q + (size_t)t * BB * S_DIM;
            sQ.m_o = out + OFF_QM + (size_t)t * BB * S_DIM;
            sQ.s_o = out + OFF_QS + (size_t)t * BB * S_DIM;
            sQ.samp_o = out + OFF_POST + (size_t)t * BB * S_DIM;
            sQ.sp_h = st_h; sQ.sp_l = st_l;
            mma_gemm<64, 256><<<dim3(1, BB / BMT, 2), 256, SM64>>>(sP, sQ, 64, H_DIM, 10, 2);
        }

        if (t + 1 < T_STEPS) {   // rnn(t+1) = elu(rnn_pre[t+1] + post @ Ws^T)   (N=600, K=32)
            TSet s = z;
            s.Ahi = st_h; s.Alo = st_l; s.Whi = Ws_h; s.Wlo = Ws_l;
            s.extra = rnnpre + (size_t)(t + 1) * BB * H_DIM; s.Chi = rnn_h; s.Clo = rnn_l;
            mma_gemm<128, 512><<<dim3(5, BB / BMT, 1), 512, SM128>>>(s, s, H_DIM, S_DIM, 1, 1);
        }
    }
}